// round 8
// baseline (speedup 1.0000x reference)
#include <cuda_runtime.h>
#include <cuda_bf16.h>
#include <cstdint>

#define D        4096
#define NE       64
#define TOPK     8
#define NCAND    12
#define BM       64
#define KC       32
#define NTHREADS 256
#define NTOK     16384
#define GAP_THR  5e-5f

// Scratch (device globals: no allocation allowed in kernel_launch).
__device__ int g_cand[NTOK * NCAND];
__device__ int g_list[NTOK];
__device__ int g_cnt;

__device__ __forceinline__ unsigned long long pk2(float lo, float hi) {
    unsigned long long r;
    asm("mov.b64 %0, {%1, %2};" : "=l"(r) : "f"(lo), "f"(hi));
    return r;
}

__device__ __forceinline__ void fma2(unsigned long long& acc,
                                     unsigned long long a,
                                     unsigned long long b) {
    asm("fma.rn.f32x2 %0, %1, %2, %0;" : "+l"(acc) : "l"(a), "l"(b));
}

__device__ __forceinline__ float flo(unsigned long long v) {
    return __int_as_float((int)(unsigned)(v & 0xffffffffull));
}
__device__ __forceinline__ float fhi(unsigned long long v) {
    return __int_as_float((int)(unsigned)(v >> 32));
}

// Neumaier compensated add: s += x, error into c.
__device__ __forceinline__ void neum(float& s, float& c, float x) {
    float t = s + x;
    float z = (fabsf(s) >= fabsf(x)) ? ((s - t) + x) : ((x - t) + s);
    c += z;
    s = t;
}

__global__ void reset_kernel() { g_cnt = 0; }

__global__ __launch_bounds__(NTHREADS, 2)
void router_kernel(const float* __restrict__ A,
                   const float* __restrict__ W,
                   const float* __restrict__ bias,
                   float* __restrict__ out,
                   int write_idx)
{
    __shared__ union {
        struct {
            float As[KC * 68];    // A transposed [k][m], pitch 68
            float Ws[KC * 128];   // W duplicated (w,w) pairs: [k][2e]
        } g;
        float Ss[BM * 65];        // score matrix, pitch 65 (odd -> conflict-free)
    } sm;

    const int tid = threadIdx.x;
    const int tg  = tid & 15;     // token group: tokens 4*tg .. 4*tg+3
    const int eg  = tid >> 4;     // expert group: experts 4*eg .. 4*eg+3
    const int m0  = blockIdx.x * BM;
    const float* Ablk = A + (size_t)m0 * D;

    unsigned long long acc[8];
#pragma unroll
    for (int i = 0; i < 8; i++) acc[i] = 0ull;

    const int r0 = tid >> 3;            // 0..31
    const int c4 = (tid & 7) * 4;       // float4 column within K-chunk

    float4 pa0 = *(const float4*)&Ablk[(size_t)r0 * D + c4];
    float4 pa1 = *(const float4*)&Ablk[(size_t)(r0 + 32) * D + c4];
    float4 pw0 = *(const float4*)&W[(size_t)r0 * D + c4];
    float4 pw1 = *(const float4*)&W[(size_t)(r0 + 32) * D + c4];

    for (int kc = 0; kc < D / KC; kc++) {
        const float* a0 = (const float*)&pa0;
        const float* a1 = (const float*)&pa1;
        const float* w0 = (const float*)&pw0;
        const float* w1 = (const float*)&pw1;
#pragma unroll
        for (int j = 0; j < 4; j++) {
            sm.g.As[(c4 + j) * 68 + r0]      = a0[j];
            sm.g.As[(c4 + j) * 68 + r0 + 32] = a1[j];
            *(unsigned long long*)&sm.g.Ws[(c4 + j) * 128 + 2 * r0]        = pk2(w0[j], w0[j]);
            *(unsigned long long*)&sm.g.Ws[(c4 + j) * 128 + 2 * (r0 + 32)] = pk2(w1[j], w1[j]);
        }
        __syncthreads();

        if (kc + 1 < D / KC) {
            const int k0 = (kc + 1) * KC;
            pa0 = *(const float4*)&Ablk[(size_t)r0 * D + k0 + c4];
            pa1 = *(const float4*)&Ablk[(size_t)(r0 + 32) * D + k0 + c4];
            pw0 = *(const float4*)&W[(size_t)r0 * D + k0 + c4];
            pw1 = *(const float4*)&W[(size_t)(r0 + 32) * D + k0 + c4];
        }

#pragma unroll 8
        for (int k = 0; k < KC; k++) {
            unsigned long long a01 = *(const unsigned long long*)&sm.g.As[k * 68 + 4 * tg];
            unsigned long long a23 = *(const unsigned long long*)&sm.g.As[k * 68 + 4 * tg + 2];
            const unsigned long long* wrow =
                (const unsigned long long*)&sm.g.Ws[k * 128 + 8 * eg];
#pragma unroll
            for (int e = 0; e < 4; e++) {
                unsigned long long w = wrow[e];
                fma2(acc[e],     a01, w);
                fma2(acc[4 + e], a23, w);
            }
        }
        __syncthreads();
    }

    // Scatter scores (+bias) into shared score matrix.
#pragma unroll
    for (int e = 0; e < 4; e++) {
        const int ex = 4 * eg + e;
        const float be = __ldg(&bias[ex]);
        sm.Ss[(4 * tg + 0) * 65 + ex] = flo(acc[e])     + be;
        sm.Ss[(4 * tg + 1) * 65 + ex] = fhi(acc[e])     + be;
        sm.Ss[(4 * tg + 2) * 65 + ex] = flo(acc[4 + e]) + be;
        sm.Ss[(4 * tg + 3) * 65 + ex] = fhi(acc[4 + e]) + be;
    }
    __syncthreads();

    // Top-12 selection; finalize directly unless a near-tie requires refinement.
    if (tid < BM) {
        float* row = &sm.Ss[tid * 65];
        const int g = m0 + tid;
        const float NEG_INF = __int_as_float(0xff800000);

        float vals[NCAND];
        int   idxs[NCAND];
#pragma unroll
        for (int i = 0; i < NCAND; i++) {
            float best = NEG_INF;
            int   bi   = 0;
            for (int e = 0; e < NE; e++) {
                float v = row[e];
                if (v > best) { best = v; bi = e; }   // strict > : lowest index wins ties
            }
            row[bi] = NEG_INF;
            vals[i] = best;
            idxs[i] = bi;
        }

        // Candidate list for the refinement pass.
#pragma unroll
        for (int i = 0; i < NCAND; i++) g_cand[g * NCAND + i] = idxs[i];

        // Near-tie detection over the gaps that determine output (ranks 1..8
        // ordering + rank8/rank9 membership boundary).
        bool flagged = false;
#pragma unroll
        for (int i = 0; i < 9; i++)
            if (vals[i] - vals[i + 1] < GAP_THR) flagged = true;

        if (flagged) {
            int pos = atomicAdd(&g_cnt, 1);
            g_list[pos] = g;
        } else {
            const float mx = vals[0];
            float ex[TOPK];
            float s = 0.f;
#pragma unroll
            for (int i = 0; i < TOPK; i++) { ex[i] = expf(vals[i] - mx); s += ex[i]; }
            const float inv = 1.f / s;
#pragma unroll
            for (int i = 0; i < TOPK; i++)
                out[(size_t)g * TOPK + i] = ex[i] * inv;
            if (write_idx) {
#pragma unroll
                for (int i = 0; i < TOPK; i++)
                    out[(size_t)NTOK * TOPK + (size_t)g * TOPK + i] = (float)idxs[i];
            }
        }
    }
}

// Phase 2: near-exact recomputation of the 12 candidate scores for flagged
// tokens. 128 threads/block: 4 warps x 3 experts, one warp-wide compensated
// dot product per expert.
__global__ __launch_bounds__(128)
void refine_kernel(const float* __restrict__ A,
                   const float* __restrict__ W,
                   const float* __restrict__ bias,
                   float* __restrict__ out,
                   int write_idx)
{
    __shared__ float rv[NCAND];

    const int n = g_cnt;
    const int wp = threadIdx.x >> 5;
    const int l  = threadIdx.x & 31;

    for (int it = blockIdx.x; it < n; it += gridDim.x) {
        const int tok = g_list[it];
        const float4* A4 = (const float4*)(A + (size_t)tok * D);

#pragma unroll
        for (int c = 0; c < 3; c++) {
            const int ci = wp * 3 + c;
            const int e  = g_cand[tok * NCAND + ci];
            const float4* W4 = (const float4*)(W + (size_t)e * D);

            float s = 0.f, comp = 0.f;
            for (int j = 0; j < D / 4 / 32; j++) {
                float4 a  = A4[l + 32 * j];
                float4 wv = W4[l + 32 * j];
                neum(s, comp, a.x * wv.x);
                neum(s, comp, a.y * wv.y);
                neum(s, comp, a.z * wv.z);
                neum(s, comp, a.w * wv.w);
            }
            // Warp reduction with exact TwoSum on the leading terms.
#pragma unroll
            for (int off = 16; off; off >>= 1) {
                float s2 = __shfl_down_sync(0xffffffffu, s,    off);
                float c2 = __shfl_down_sync(0xffffffffu, comp, off);
                float t  = s + s2;
                float bp = t - s;
                float er = (s - (t - bp)) + (s2 - bp);
                s = t;
                comp = comp + c2 + er;
            }
            if (l == 0) rv[ci] = (s + comp) + bias[e];
        }
        __syncthreads();

        if (threadIdx.x == 0) {
            float v[NCAND]; int id[NCAND]; bool used[NCAND];
#pragma unroll
            for (int i = 0; i < NCAND; i++) {
                v[i] = rv[i]; id[i] = g_cand[tok * NCAND + i]; used[i] = false;
            }
            float tv[TOPK]; int ti[TOPK];
#pragma unroll
            for (int i = 0; i < TOPK; i++) {
                int   bj = -1;
                float bv = 0.f;
                int   be = 1 << 30;
                for (int j = 0; j < NCAND; j++) {
                    if (used[j]) continue;
                    if (bj < 0 || v[j] > bv || (v[j] == bv && id[j] < be)) {
                        bj = j; bv = v[j]; be = id[j];
                    }
                }
                used[bj] = true;
                tv[i] = bv;
                ti[i] = be;
            }
            const float mx = tv[0];
            float ex[TOPK];
            float ss = 0.f;
#pragma unroll
            for (int i = 0; i < TOPK; i++) { ex[i] = expf(tv[i] - mx); ss += ex[i]; }
            const float inv = 1.f / ss;
#pragma unroll
            for (int i = 0; i < TOPK; i++)
                out[(size_t)tok * TOPK + i] = ex[i] * inv;
            if (write_idx) {
#pragma unroll
                for (int i = 0; i < TOPK; i++)
                    out[(size_t)NTOK * TOPK + (size_t)tok * TOPK + i] = (float)ti[i];
            }
        }
        __syncthreads();
    }
}

extern "C" void kernel_launch(void* const* d_in, const int* in_sizes, int n_in,
                              void* d_out, int out_size) {
    const float* A = (const float*)d_in[0];   // inputs [16384, 4096]
    const float* W = (const float*)d_in[1];   // W      [64, 4096]
    const float* b = (const float*)d_in[2];   // b      [64]
    float* out = (float*)d_out;

    const int write_idx = (out_size >= 2 * NTOK * TOPK) ? 1 : 0;

    reset_kernel<<<1, 1>>>();
    router_kernel<<<NTOK / BM, NTHREADS>>>(A, W, b, out, write_idx);
    refine_kernel<<<256, 128>>>(A, W, b, out, write_idx);
}

// round 13
// speedup vs baseline: 2.7315x; 2.7315x over previous
#include <cuda_runtime.h>
#include <cuda_bf16.h>
#include <cstdint>

#define D        4096
#define NE       64
#define TOPK     8
#define NCAND    12
#define NTOK     16384
#define GAP_THR  5e-5f

#define BM2      128            // tokens per CTA
#define CK       64             // K per chunk (64 bf16 = 128B = SW128 row)
#define NCHUNK   (D / CK)       // 64
#define NTHR     256            // 8 warps, all produce + all compute

// Dynamic smem layout
#define OFF_BIAS   0
#define OFF_TILES  512          // 128B-aligned (keeps swizzle bank map intact)
#define A_BYTES    (BM2 * 128)                  // 16 KB per level
#define W_BYTES    (NE * 128)                   // 8 KB per level
#define BUF_BYTES  (2 * A_BYTES + 2 * W_BYTES)  // 48 KB per buffer
#define SMEM_TOTAL (OFF_TILES + 2 * BUF_BYTES)  // ~96.5 KB

// Scratch (device globals: no allocation allowed).
__device__ int g_cand[NTOK * NCAND];
__device__ int g_list[NTOK];
__device__ int g_cnt;
__device__ __align__(16) __nv_bfloat16 g_W2[2][NE * D];   // W split: hi, lo bf16

// ---------------- helpers ----------------
__device__ __forceinline__ uint32_t smem_u32(const void* p) {
    uint32_t a;
    asm("{ .reg .u64 t; cvta.to.shared.u64 t, %1; cvt.u32.u64 %0, t; }" : "=r"(a) : "l"(p));
    return a;
}
#define SWZ(off) ((off) ^ (((off) >> 3) & 0x70))

#define STS128(addr, r0, r1, r2, r3) \
    asm volatile("st.shared.v4.b32 [%0], {%1, %2, %3, %4};" \
                 :: "r"(addr), "r"(r0), "r"(r1), "r"(r2), "r"(r3) : "memory")

#define LDSM4(r, addr) \
    asm volatile("ldmatrix.sync.aligned.m8n8.x4.shared.b16 {%0,%1,%2,%3}, [%4];" \
        : "=r"((r)[0]), "=r"((r)[1]), "=r"((r)[2]), "=r"((r)[3]) : "r"(addr))

#define MMA16816(c, a, b0, b1) \
    asm volatile("mma.sync.aligned.m16n8k16.row.col.f32.bf16.bf16.f32 " \
        "{%0,%1,%2,%3}, {%4,%5,%6,%7}, {%8,%9}, {%0,%1,%2,%3};" \
        : "+f"((c)[0]), "+f"((c)[1]), "+f"((c)[2]), "+f"((c)[3]) \
        : "r"((a)[0]), "r"((a)[1]), "r"((a)[2]), "r"((a)[3]), "r"(b0), "r"(b1))

// 2-level bf16 split of a packed f32 pair.
__device__ __forceinline__ void split1(float a, float b, uint32_t& hi, uint32_t& lo) {
    __nv_bfloat162 h = __floats2bfloat162_rn(a, b);
    float ra = a - __bfloat162float(h.x);
    float rb = b - __bfloat162float(h.y);
    __nv_bfloat162 l = __floats2bfloat162_rn(ra, rb);
    hi = *reinterpret_cast<uint32_t*>(&h);
    lo = *reinterpret_cast<uint32_t*>(&l);
}

// Neumaier compensated add (refine pass).
__device__ __forceinline__ void neum(float& s, float& c, float x) {
    float t = s + x;
    float z = (fabsf(s) >= fabsf(x)) ? ((s - t) + x) : ((x - t) + s);
    c += z;
    s = t;
}

__global__ void reset_kernel() { g_cnt = 0; }

// Pre-split W into hi/lo bf16 (runs every launch; ~1 MB traffic).
__global__ void prep_w_kernel(const float* __restrict__ W) {
    int i = blockIdx.x * 256 + threadIdx.x;
    if (i < NE * D) {
        float w = W[i];
        __nv_bfloat16 b0 = __float2bfloat16(w);
        float r1 = w - __bfloat162float(b0);
        __nv_bfloat16 b1 = __float2bfloat16(r1);
        g_W2[0][i] = b0;
        g_W2[1][i] = b1;
    }
}

// ---------------- main router: mma.sync bf16-split GEMM + fused top-k ----------------
__global__ __launch_bounds__(NTHR, 1)
void router_kernel(const float* __restrict__ A,
                   const float* __restrict__ bias,
                   float* __restrict__ out,
                   int write_idx)
{
    extern __shared__ char smem[];
    const uint32_t sb  = smem_u32(smem);
    const int tid = threadIdx.x;
    const int wid = tid >> 5;
    const int lid = tid & 31;
    const int m0  = blockIdx.x * BM2;

    if (tid < NE) ((float*)(smem + OFF_BIAS))[tid] = bias[tid];

    // ---- producer mapping: thread = (token row, 32-element k-half) ----
    const int arow = tid >> 1;
    const int akin = (tid & 1) * 32;
    const float* Arow = A + (size_t)(m0 + arow) * D + akin;

    uint32_t aoff[4];
#pragma unroll
    for (int g = 0; g < 4; g++)
        aoff[g] = SWZ((uint32_t)arow * 128 + (uint32_t)(akin + 8 * g) * 2);

    // W: 2 levels x 64 rows x 8 16B-units = 1024 units over 256 threads (4 each)
    int      wlv[4], welem[4];
    uint32_t woff[4];
#pragma unroll
    for (int i = 0; i < 4; i++) {
        int u    = tid + 256 * i;
        wlv[i]   = u >> 9;
        int rem  = u & 511;
        int wrow = rem >> 3;
        int wgrp = rem & 7;
        welem[i] = wrow * D + wgrp * 8;
        woff[i]  = SWZ((uint32_t)wrow * 128 + (uint32_t)wgrp * 16);
    }

    // ---- compute mapping: warp owns rows 16*wid..16*wid+15, all 64 experts ----
    const int mrow = wid * 16;
    // Unswizzled ldmatrix base offsets; K-advance (ks*32) is added BEFORE the
    // swizzle (post-swizzle addition carries into row bits -> OOB, the R10 bug).
    // A x4: lanes 0-15 -> rows m0..15 (k0-7 bytes 0-15), lanes 16-31 -> +16B (k8-15)
    const uint32_t a_base = (uint32_t)(mrow + (lid & 15)) * 128 + (uint32_t)(lid >> 4) * 16;
    // B x4 quarters: {experts r0-7 k0, r0-7 k8, r8-15 k0, r8-15 k8} within a 16-expert group
    const int q = lid >> 3;
    const uint32_t w_base = (uint32_t)((q >> 1) * 8 + (lid & 7)) * 128 + (uint32_t)(q & 1) * 16;

    uint32_t a_sw[4], w_sw[4];
#pragma unroll
    for (int ks = 0; ks < 4; ks++) {
        a_sw[ks] = SWZ(a_base + ks * 32);   // col = 0..112 < 128, no carry
        w_sw[ks] = SWZ(w_base + ks * 32);
    }

    float acc[32];
#pragma unroll
    for (int i = 0; i < 32; i++) acc[i] = 0.f;

    // prefetch chunk 0
    float4 pa[8];
    uint4  pw[4];
    {
        const float4* ag = reinterpret_cast<const float4*>(Arow);
#pragma unroll
        for (int j = 0; j < 8; j++) pa[j] = ag[j];
#pragma unroll
        for (int i = 0; i < 4; i++)
            pw[i] = *reinterpret_cast<const uint4*>(&g_W2[wlv[i]][(size_t)welem[i]]);
    }

    for (int chunk = 0; chunk < NCHUNK; chunk++) {
        const int buf = chunk & 1;
        const uint32_t tb = sb + OFF_TILES + buf * BUF_BYTES;

        // ---- store prefetched chunk (A split to hi/lo, W pre-split copy) ----
#pragma unroll
        for (int g = 0; g < 4; g++) {
            float4 x = pa[2 * g];
            float4 y = pa[2 * g + 1];
            uint32_t h[4], l[4];
            split1(x.x, x.y, h[0], l[0]);
            split1(x.z, x.w, h[1], l[1]);
            split1(y.x, y.y, h[2], l[2]);
            split1(y.z, y.w, h[3], l[3]);
            STS128(tb + 0 * A_BYTES + aoff[g], h[0], h[1], h[2], h[3]);
            STS128(tb + 1 * A_BYTES + aoff[g], l[0], l[1], l[2], l[3]);
        }
#pragma unroll
        for (int i = 0; i < 4; i++)
            STS128(tb + 2 * A_BYTES + (uint32_t)wlv[i] * W_BYTES + woff[i],
                   pw[i].x, pw[i].y, pw[i].z, pw[i].w);
        __syncthreads();

        // ---- prefetch next chunk (overlaps compute) ----
        if (chunk + 1 < NCHUNK) {
            const int k0 = (chunk + 1) * CK;
            const float4* ag = reinterpret_cast<const float4*>(Arow + k0);
#pragma unroll
            for (int j = 0; j < 8; j++) pa[j] = ag[j];
#pragma unroll
            for (int i = 0; i < 4; i++)
                pw[i] = *reinterpret_cast<const uint4*>(&g_W2[wlv[i]][(size_t)welem[i] + k0]);
        }

        // ---- compute: 4 k16-steps x (2 A-ldsm + 8 B-ldsm + 24 mma) ----
        const uint32_t Ah = tb + 0 * A_BYTES;
        const uint32_t Al = tb + 1 * A_BYTES;
        const uint32_t Wh = tb + 2 * A_BYTES;
        const uint32_t Wl = Wh + W_BYTES;
#pragma unroll
        for (int ks = 0; ks < 4; ks++) {
            uint32_t ah[4], al[4];
            LDSM4(ah, Ah + a_sw[ks]);
            LDSM4(al, Al + a_sw[ks]);
#pragma unroll
            for (int p = 0; p < 4; p++) {
                // p*2048 = 16-expert stride: row-aligned, commutes with SW128
                uint32_t bh[4], bl[4];
                LDSM4(bh, Wh + p * 2048 + w_sw[ks]);
                LDSM4(bl, Wl + p * 2048 + w_sw[ks]);
                float* c0 = &acc[(2 * p) * 4];
                float* c1 = &acc[(2 * p + 1) * 4];
                MMA16816(c0, ah, bh[0], bh[1]);   // hi*hi
                MMA16816(c0, ah, bl[0], bl[1]);   // hi*lo
                MMA16816(c0, al, bh[0], bh[1]);   // lo*hi
                MMA16816(c1, ah, bh[2], bh[3]);
                MMA16816(c1, ah, bl[2], bl[3]);
                MMA16816(c1, al, bh[2], bh[3]);
            }
        }
        // Double buffer + one sync/iter is race-free: a warp reaches iter i+2's
        // store of buffer b only after passing iter i+1's barrier, which every
        // warp reaches only after finishing its iter-i compute on buffer b.
    }
    __syncthreads();

    // ---- scores -> smem (pitch 65, conflict-free scans), +bias ----
    float* Ss = (float*)(smem + OFF_TILES);
    const float* bs = (const float*)(smem + OFF_BIAS);
    {
        const int col0 = (lid & 3) * 2;
        const int row  = mrow + (lid >> 2);
#pragma unroll
        for (int t = 0; t < 8; t++) {
            const int col = 8 * t + col0;
            Ss[row * 65 + col]           = acc[4 * t + 0] + bs[col];
            Ss[row * 65 + col + 1]       = acc[4 * t + 1] + bs[col + 1];
            Ss[(row + 8) * 65 + col]     = acc[4 * t + 2] + bs[col];
            Ss[(row + 8) * 65 + col + 1] = acc[4 * t + 3] + bs[col + 1];
        }
    }
    __syncthreads();

    // ---- per-token top-12, flag near-ties, finalize the rest ----
    if (tid < BM2) {
        float* row = &Ss[tid * 65];
        const int g = m0 + tid;
        const float NEG_INF = __int_as_float(0xff800000);

        float vals[NCAND];
        int   idxs[NCAND];
#pragma unroll
        for (int i = 0; i < NCAND; i++) {
            float best = NEG_INF;
            int   bi   = 0;
            for (int e = 0; e < NE; e++) {
                float v = row[e];
                if (v > best) { best = v; bi = e; }   // strict > : lowest index wins ties
            }
            row[bi] = NEG_INF;
            vals[i] = best;
            idxs[i] = bi;
        }

#pragma unroll
        for (int i = 0; i < NCAND; i++) g_cand[g * NCAND + i] = idxs[i];

        bool flagged = false;
#pragma unroll
        for (int i = 0; i < 9; i++)
            if (vals[i] - vals[i + 1] < GAP_THR) flagged = true;

        if (flagged) {
            int pos = atomicAdd(&g_cnt, 1);
            g_list[pos] = g;
        } else {
            const float mx = vals[0];
            float ex[TOPK];
            float s = 0.f;
#pragma unroll
            for (int i = 0; i < TOPK; i++) { ex[i] = expf(vals[i] - mx); s += ex[i]; }
            const float inv = 1.f / s;
#pragma unroll
            for (int i = 0; i < TOPK; i++)
                out[(size_t)g * TOPK + i] = ex[i] * inv;
            if (write_idx) {
#pragma unroll
                for (int i = 0; i < TOPK; i++)
                    out[(size_t)NTOK * TOPK + (size_t)g * TOPK + i] = (float)idxs[i];
            }
        }
    }
}

// ---------------- Phase 2: exact recomputation for near-tie tokens ----------------
__global__ __launch_bounds__(128)
void refine_kernel(const float* __restrict__ A,
                   const float* __restrict__ W,
                   const float* __restrict__ bias,
                   float* __restrict__ out,
                   int write_idx)
{
    __shared__ float rv[NCAND];

    const int n  = g_cnt;
    const int wp = threadIdx.x >> 5;
    const int l  = threadIdx.x & 31;

    for (int it = blockIdx.x; it < n; it += gridDim.x) {
        const int tok = g_list[it];
        const float4* A4 = (const float4*)(A + (size_t)tok * D);

#pragma unroll
        for (int c = 0; c < 3; c++) {
            const int ci = wp * 3 + c;
            const int e  = g_cand[tok * NCAND + ci];
            const float4* W4 = (const float4*)(W + (size_t)e * D);

            float s = 0.f, comp = 0.f;
            for (int j = 0; j < D / 4 / 32; j++) {
                float4 a  = A4[l + 32 * j];
                float4 wv = W4[l + 32 * j];
                neum(s, comp, a.x * wv.x);
                neum(s, comp, a.y * wv.y);
                neum(s, comp, a.z * wv.z);
                neum(s, comp, a.w * wv.w);
            }
#pragma unroll
            for (int off = 16; off; off >>= 1) {
                float s2 = __shfl_down_sync(0xffffffffu, s,    off);
                float c2 = __shfl_down_sync(0xffffffffu, comp, off);
                float t  = s + s2;
                float bp = t - s;
                float er = (s - (t - bp)) + (s2 - bp);
                s = t;
                comp = comp + c2 + er;
            }
            if (l == 0) rv[ci] = (s + comp) + bias[e];
        }
        __syncthreads();

        if (threadIdx.x == 0) {
            float v[NCAND]; int id[NCAND]; bool usedv[NCAND];
#pragma unroll
            for (int i = 0; i < NCAND; i++) {
                v[i] = rv[i]; id[i] = g_cand[tok * NCAND + i]; usedv[i] = false;
            }
            float tv[TOPK]; int ti[TOPK];
#pragma unroll
            for (int i = 0; i < TOPK; i++) {
                int   bj = -1;
                float bv = 0.f;
                int   be = 1 << 30;
                for (int j = 0; j < NCAND; j++) {
                    if (usedv[j]) continue;
                    if (bj < 0 || v[j] > bv || (v[j] == bv && id[j] < be)) {
                        bj = j; bv = v[j]; be = id[j];
                    }
                }
                usedv[bj] = true;
                tv[i] = bv;
                ti[i] = be;
            }
            const float mx = tv[0];
            float ex[TOPK];
            float ss = 0.f;
#pragma unroll
            for (int i = 0; i < TOPK; i++) { ex[i] = expf(tv[i] - mx); ss += ex[i]; }
            const float inv = 1.f / ss;
#pragma unroll
            for (int i = 0; i < TOPK; i++)
                out[(size_t)tok * TOPK + i] = ex[i] * inv;
            if (write_idx) {
#pragma unroll
                for (int i = 0; i < TOPK; i++)
                    out[(size_t)NTOK * TOPK + (size_t)tok * TOPK + i] = (float)ti[i];
            }
        }
        __syncthreads();
    }
}

extern "C" void kernel_launch(void* const* d_in, const int* in_sizes, int n_in,
                              void* d_out, int out_size) {
    const float* A = (const float*)d_in[0];   // inputs [16384, 4096]
    const float* W = (const float*)d_in[1];   // W      [64, 4096]
    const float* b = (const float*)d_in[2];   // b      [64]
    float* out = (float*)d_out;

    const int write_idx = (out_size >= 2 * NTOK * TOPK) ? 1 : 0;

    cudaFuncSetAttribute(router_kernel, cudaFuncAttributeMaxDynamicSharedMemorySize, SMEM_TOTAL);

    reset_kernel<<<1, 1>>>();
    prep_w_kernel<<<(NE * D + 255) / 256, 256>>>(W);
    router_kernel<<<NTOK / BM2, NTHR, SMEM_TOTAL>>>(A, b, out, write_idx);
    refine_kernel<<<256, 128>>>(A, W, b, out, write_idx);
}